// round 1
// baseline (speedup 1.0000x reference)
#include <cuda_runtime.h>
#include <math.h>

// Problem constants
#define V_ 50000
#define E_ 300
#define T_ 512
#define U_ 256
#define G_ 768      // 3*U
#define B_ 64
#define C_ 20
#define M_ (B_*T_)  // 32768 rows for the big GEMMs

// ---------------- static device scratch (no runtime allocation) ----------------
__device__ float g_e [(size_t)M_ * E_];        // embedded input  [B*T, 300]   39.3 MB
__device__ float g_xw[2][(size_t)M_ * G_];     // xw per direction [B*T, 768]  2x100.7 MB (reused for layer2)
__device__ float g_h1[(size_t)M_ * 2 * U_];    // layer1 output   [B,T,512]    67 MB
__device__ float g_hs2[2][2][B_][U_];          // layer2 h double buffer [parity][dir][B][U]
__device__ float g_h2[B_][2 * U_];             // final states    [B,512]
__device__ unsigned g_count;                   // grid barrier (monotonic)

// ---------------- init ----------------
__global__ void init_k() { g_count = 0u; }

// ---------------- embedding gather: e = emb[x] ----------------
__global__ void gather_k(const int* __restrict__ x, const float* __restrict__ emb) {
    size_t i = (size_t)blockIdx.x * blockDim.x + threadIdx.x;
    if (i >= (size_t)M_ * E_) return;
    int bt = (int)(i / E_);
    int c  = (int)(i - (size_t)bt * E_);
    g_e[i] = emb[(size_t)x[bt] * E_ + c];
}

// ---------------- SGEMM with fused bias: C[M,N] = A[M,K] @ W[K,N] + bias[N] ----------------
// BM=128, BN=64, BK=16, 256 threads, thread tile 8x4
__global__ __launch_bounds__(256, 2) void sgemm_bias_k(
    const float* __restrict__ A, const float* __restrict__ W,
    const float* __restrict__ bias, float* __restrict__ C,
    int Mdim, int Ndim, int Kdim)
{
    __shared__ float As[16][128];
    __shared__ float Bs[16][64];

    const int tid = threadIdx.x;
    const int tx = tid & 15;    // n-dim (16 groups of 4 cols)
    const int ty = tid >> 4;    // m-dim (16 groups of 8 rows)
    const int m0 = blockIdx.y * 128;
    const int n0 = blockIdx.x * 64;

    float acc[8][4];
#pragma unroll
    for (int i = 0; i < 8; i++)
#pragma unroll
        for (int j = 0; j < 4; j++) acc[i][j] = 0.f;

    const int ktiles = (Kdim + 15) >> 4;
    for (int kt = 0; kt < ktiles; kt++) {
        const int k0 = kt << 4;
        // Load A tile (128 x 16) as 512 float4 slots, transpose into As[k][m]
#pragma unroll
        for (int q = 0; q < 2; q++) {
            int s = tid + q * 256;          // 0..511
            int row = s >> 2;               // 0..127
            int kc  = s & 3;                // which float4 in the 16-col row
            int kcol = k0 + kc * 4;
            float4 v = make_float4(0.f, 0.f, 0.f, 0.f);
            if (kcol < Kdim)                // K is a multiple of 4, so whole float4 valid
                v = *(const float4*)&A[(size_t)(m0 + row) * Kdim + kcol];
            As[kc * 4 + 0][row] = v.x;
            As[kc * 4 + 1][row] = v.y;
            As[kc * 4 + 2][row] = v.z;
            As[kc * 4 + 3][row] = v.w;
        }
        // Load B tile (16 x 64): one float4 per thread
        {
            int krow = tid >> 4;            // 0..15
            int nc   = tid & 15;            // 0..15
            float4 v = make_float4(0.f, 0.f, 0.f, 0.f);
            if (k0 + krow < Kdim)
                v = *(const float4*)&W[(size_t)(k0 + krow) * Ndim + n0 + nc * 4];
            *(float4*)&Bs[krow][nc * 4] = v;
        }
        __syncthreads();

#pragma unroll
        for (int kk = 0; kk < 16; kk++) {
            float4 a0 = *(const float4*)&As[kk][ty * 8];
            float4 a1 = *(const float4*)&As[kk][ty * 8 + 4];
            float4 bv = *(const float4*)&Bs[kk][tx * 4];
            float a[8] = {a0.x, a0.y, a0.z, a0.w, a1.x, a1.y, a1.z, a1.w};
            float bb[4] = {bv.x, bv.y, bv.z, bv.w};
#pragma unroll
            for (int i = 0; i < 8; i++)
#pragma unroll
                for (int j = 0; j < 4; j++)
                    acc[i][j] = fmaf(a[i], bb[j], acc[i][j]);
        }
        __syncthreads();
    }

    // Epilogue: add bias, store
#pragma unroll
    for (int i = 0; i < 8; i++) {
        size_t rowoff = (size_t)(m0 + ty * 8 + i) * Ndim + n0 + tx * 4;
#pragma unroll
        for (int j = 0; j < 4; j++)
            C[rowoff + j] = acc[i][j] + bias[n0 + tx * 4 + j];
    }
}

// ---------------- grid barrier (monotonic counter, no reset) ----------------
__device__ __forceinline__ void grid_sync(unsigned target) {
    __syncthreads();
    if (threadIdx.x == 0) {
        __threadfence();
        atomicAdd(&g_count, 1u);
        while (*(volatile unsigned*)&g_count < target) { __nanosleep(32); }
    }
    __syncthreads();
}

// ---------------- persistent bidirectional GRU scan ----------------
// grid = 128 CTAs: dir(2) x batch-block(4, 16 batches each) x u-block(16, 16 units each)
// Each CTA keeps its rk slice (3 gates x 256 x 16) in smem; h is exchanged via L2.
#define SCAN_SMEM_FLOATS (3*256*16 + 16*260)
__global__ __launch_bounds__(256, 1) void scan_k(
    const float* __restrict__ rkf, const float* __restrict__ rbf,  // recurrent weights/bias row1, fwd
    const float* __restrict__ rkb, const float* __restrict__ rbb,  // bwd
    int layer)
{
    extern __shared__ float sm[];
    float* wz = sm;                 // [256][16]
    float* wr = sm + 4096;
    float* wh = sm + 8192;
    float* hs = sm + 12288;         // [16][260] padded rows

    const int cta  = blockIdx.x;
    const int dir  = cta >> 6;      // 0 = fwd, 1 = bwd
    const int rem  = cta & 63;
    const int b0   = (rem >> 4) * 16;   // batch base
    const int u0   = (rem & 15) * 16;   // unit base

    const int tid = threadIdx.x;
    const int b_l = tid >> 4;       // 0..15 local batch
    const int u_l = tid & 15;       // 0..15 local unit
    const int u   = u0 + u_l;       // global unit
    const int b   = b0 + b_l;       // global batch

    const float* rk = dir ? rkb : rkf;
    const float* rb = dir ? rbb : rbf;
    const float* xw = g_xw[dir];

    // Load recurrent-weight slice into smem: wg[k][u_l] = rk[k*G + gate*U + u0+u_l]
    for (int i = tid; i < 4096; i += 256) {
        int k = i >> 4, uu = i & 15;
        wz[i] = rk[(size_t)k * G_ +           u0 + uu];
        wr[i] = rk[(size_t)k * G_ + U_  +     u0 + uu];
        wh[i] = rk[(size_t)k * G_ + 2 * U_ +  u0 + uu];
    }
    const float bz = rb[u], br = rb[U_ + u], bh = rb[2 * U_ + u];

    const unsigned nctas = gridDim.x;

    for (int s = 0; s < T_; s++) {
        const int t  = dir ? (T_ - 1 - s) : s;
        // ---- stage h_{prev} for this CTA's 16 batches (full 256 units) ----
        if (s == 0) {
            for (int i = tid; i < 16 * 260; i += 256) hs[i] = 0.f;
        } else {
            const int tp = dir ? (t + 1) : (t - 1);
            for (int i = tid; i < 1024; i += 256) {   // 1024 float4 = 16 x 64
                int bb = i >> 6, kf = i & 63;
                float4 v;
                if (layer == 1) {
                    v = __ldcg((const float4*)&g_h1[((size_t)(b0 + bb) * T_ + tp) * (2 * U_) + dir * U_ + kf * 4]);
                } else {
                    v = __ldcg((const float4*)&g_hs2[(s - 1) & 1][dir][b0 + bb][kf * 4]);
                }
                *(float4*)&hs[bb * 260 + kf * 4] = v;
            }
        }
        __syncthreads();

        // ---- inner = h @ rk + b1 for (b, u): three 256-long dot products ----
        float az = bz, ar = br, ah = bh;
        const float* hrow = hs + b_l * 260;
#pragma unroll 8
        for (int k = 0; k < 256; k += 4) {
            float4 h4 = *(const float4*)(hrow + k);
            const float* wzk = wz + k * 16 + u_l;
            const float* wrk = wr + k * 16 + u_l;
            const float* whk = wh + k * 16 + u_l;
            az = fmaf(h4.x, wzk[0], az); az = fmaf(h4.y, wzk[16], az);
            az = fmaf(h4.z, wzk[32], az); az = fmaf(h4.w, wzk[48], az);
            ar = fmaf(h4.x, wrk[0], ar); ar = fmaf(h4.y, wrk[16], ar);
            ar = fmaf(h4.z, wrk[32], ar); ar = fmaf(h4.w, wrk[48], ar);
            ah = fmaf(h4.x, whk[0], ah); ah = fmaf(h4.y, whk[16], ah);
            ah = fmaf(h4.z, whk[32], ah); ah = fmaf(h4.w, whk[48], ah);
        }

        // ---- gates ----
        const float* xwp = xw + ((size_t)b * T_ + t) * G_;
        float xz  = __ldg(xwp + u);
        float xr_ = __ldg(xwp + U_ + u);
        float xh  = __ldg(xwp + 2 * U_ + u);
        float z  = 1.f / (1.f + expf(-(xz  + az)));
        float r  = 1.f / (1.f + expf(-(xr_ + ar)));
        float hh = tanhf(xh + r * ah);
        float hp = hrow[u0 + u_l];
        float hn = z * hp + (1.f - z) * hh;

        // ---- publish h_t ----
        if (layer == 1) {
            __stcg(&g_h1[((size_t)b * T_ + t) * (2 * U_) + dir * U_ + u], hn);
        } else {
            __stcg(&g_hs2[s & 1][dir][b][u], hn);
            if (s == T_ - 1) g_h2[b][dir * U_ + u] = hn;   // f2 at t=T-1, b2 at t=0
        }

        if (s != T_ - 1) grid_sync((unsigned)(s + 1) * nctas);
    }
}

// ---------------- head: softmax(h2 @ wout + bout) ----------------
__global__ void head_k(const float* __restrict__ wout, const float* __restrict__ bout,
                       float* __restrict__ out)
{
    const int b = blockIdx.x, lane = threadIdx.x;
    float acc = 0.f;
    if (lane < C_) {
        acc = bout[lane];
        for (int k = 0; k < 2 * U_; k++)
            acc = fmaf(g_h2[b][k], wout[k * C_ + lane], acc);
    }
    float v = (lane < C_) ? acc : -INFINITY;
    for (int o = 16; o; o >>= 1) v = fmaxf(v, __shfl_xor_sync(0xffffffffu, v, o));
    float e = (lane < C_) ? expf(acc - v) : 0.f;
    float ssum = e;
    for (int o = 16; o; o >>= 1) ssum += __shfl_xor_sync(0xffffffffu, ssum, o);
    if (lane < C_) out[b * C_ + lane] = e / ssum;
}

// ---------------- launch ----------------
extern "C" void kernel_launch(void* const* d_in, const int* in_sizes, int n_in,
                              void* d_out, int out_size)
{
    const int*   x    = (const int*)  d_in[0];
    const float* emb  = (const float*)d_in[1];
    const float* k1f  = (const float*)d_in[2];
    const float* rk1f = (const float*)d_in[3];
    const float* b1f  = (const float*)d_in[4];
    const float* k1b  = (const float*)d_in[5];
    const float* rk1b = (const float*)d_in[6];
    const float* b1b  = (const float*)d_in[7];
    const float* k2f  = (const float*)d_in[8];
    const float* rk2f = (const float*)d_in[9];
    const float* b2f  = (const float*)d_in[10];
    const float* k2b  = (const float*)d_in[11];
    const float* rk2b = (const float*)d_in[12];
    const float* b2b  = (const float*)d_in[13];
    const float* wout = (const float*)d_in[14];
    const float* bout = (const float*)d_in[15];
    float* out = (float*)d_out;

    float *pe, *pxw0, *pxw1, *ph1;
    cudaGetSymbolAddress((void**)&pe,   g_e);
    cudaGetSymbolAddress((void**)&pxw0, g_xw);
    pxw1 = pxw0 + (size_t)M_ * G_;
    cudaGetSymbolAddress((void**)&ph1,  g_h1);

    const int scan_smem = SCAN_SMEM_FLOATS * (int)sizeof(float);  // ~65.8 KB
    cudaFuncSetAttribute(scan_k, cudaFuncAttributeMaxDynamicSharedMemorySize, scan_smem);

    // 1) embedding gather
    gather_k<<<(int)(((size_t)M_ * E_ + 255) / 256), 256>>>(x, emb);

    // 2) layer-1 input projections (both directions)
    dim3 gg(G_ / 64, M_ / 128);   // (12, 256)
    sgemm_bias_k<<<gg, 256>>>(pe, k1f, b1f, pxw0, M_, G_, E_);
    sgemm_bias_k<<<gg, 256>>>(pe, k1b, b1b, pxw1, M_, G_, E_);

    // 3) layer-1 bidirectional scan -> g_h1
    init_k<<<1, 1>>>();
    scan_k<<<128, 256, scan_smem>>>(rk1f, b1f + G_, rk1b, b1b + G_, 1);

    // 4) layer-2 input projections (reuse xw buffers)
    sgemm_bias_k<<<gg, 256>>>(ph1, k2f, b2f, pxw0, M_, G_, 2 * U_);
    sgemm_bias_k<<<gg, 256>>>(ph1, k2b, b2b, pxw1, M_, G_, 2 * U_);

    // 5) layer-2 bidirectional scan -> g_h2
    init_k<<<1, 1>>>();
    scan_k<<<128, 256, scan_smem>>>(rk2f, b2f + G_, rk2b, b2b + G_, 2);

    // 6) output head
    head_k<<<B_, 32>>>(wout, bout, out);
}

// round 4
// speedup vs baseline: 1.2036x; 1.2036x over previous
#include <cuda_runtime.h>
#include <math.h>

// Problem constants
#define V_ 50000
#define E_ 300
#define T_ 512
#define U_ 256
#define G_ 768      // 3*U
#define B_ 64
#define C_ 20
#define M_ (B_*T_)  // 32768 rows for the big GEMMs

// ---------------- static device scratch (no runtime allocation) ----------------
__device__ float g_e [(size_t)M_ * E_];        // embedded input  [B*T, 300]
__device__ float g_xw[2][(size_t)M_ * G_];     // xw per direction [B*T, 768] (reused for layer2)
__device__ float g_h1[(size_t)M_ * 2 * U_];    // layer1 output   [B,T,512]
__device__ float g_hs2[2][2][B_][U_];          // layer2 h double buffer [parity][dir][B][U]
__device__ float g_h2[B_][2 * U_];             // final states    [B,512]
__device__ unsigned g_cnt1[16];                // layer1 group barrier counters (dir*8+bblk)
__device__ unsigned g_cnt2[16];                // layer2 group barrier counters

// ---------------- embedding gather: e = emb[x]  (+ barrier counter reset) ----------------
__global__ void gather_k(const int* __restrict__ x, const float* __restrict__ emb) {
    if (blockIdx.x == 0 && threadIdx.x < 16) {
        g_cnt1[threadIdx.x] = 0u;
        g_cnt2[threadIdx.x] = 0u;
    }
    size_t i = (size_t)blockIdx.x * blockDim.x + threadIdx.x;
    if (i >= (size_t)M_ * E_) return;
    int bt = (int)(i / E_);
    int c  = (int)(i - (size_t)bt * E_);
    g_e[i] = emb[(size_t)x[bt] * E_ + c];
}

// ---------------- SGEMM with fused bias: C[M,N] = A[M,K] @ W[K,N] + bias[N] ----------------
// BM=128, BN=128, BK=16, 256 threads, 8x8 microtile
__global__ __launch_bounds__(256, 2) void sgemm_bias_k(
    const float* __restrict__ A, const float* __restrict__ W,
    const float* __restrict__ bias, float* __restrict__ Cc,
    int Mdim, int Ndim, int Kdim)
{
    __shared__ float As[16][132];
    __shared__ float Bs[16][132];

    const int tid = threadIdx.x;
    const int tx = tid & 15;    // n-dim (16 groups of 8 cols)
    const int ty = tid >> 4;    // m-dim (16 groups of 8 rows)
    const int m0 = blockIdx.y * 128;
    const int n0 = blockIdx.x * 128;

    float acc[8][8];
#pragma unroll
    for (int i = 0; i < 8; i++)
#pragma unroll
        for (int j = 0; j < 8; j++) acc[i][j] = 0.f;

    const int ktiles = (Kdim + 15) >> 4;
    for (int kt = 0; kt < ktiles; kt++) {
        const int k0 = kt << 4;
        // A tile: 128 rows x 16 k = 512 float4, transpose into As[k][m]
#pragma unroll
        for (int q = 0; q < 2; q++) {
            int s = tid + q * 256;
            int row = s >> 2;
            int kc  = s & 3;
            int kcol = k0 + kc * 4;
            float4 v = make_float4(0.f, 0.f, 0.f, 0.f);
            if (kcol < Kdim)
                v = *(const float4*)&A[(size_t)(m0 + row) * Kdim + kcol];
            As[kc * 4 + 0][row] = v.x;
            As[kc * 4 + 1][row] = v.y;
            As[kc * 4 + 2][row] = v.z;
            As[kc * 4 + 3][row] = v.w;
        }
        // B tile: 16 rows x 128 cols = 512 float4
#pragma unroll
        for (int q = 0; q < 2; q++) {
            int s = tid + q * 256;
            int krow = s >> 5;
            int nc   = s & 31;
            float4 v = make_float4(0.f, 0.f, 0.f, 0.f);
            if (k0 + krow < Kdim)
                v = *(const float4*)&W[(size_t)(k0 + krow) * Ndim + n0 + nc * 4];
            *(float4*)&Bs[krow][nc * 4] = v;
        }
        __syncthreads();

#pragma unroll
        for (int kk = 0; kk < 16; kk++) {
            float4 a0 = *(const float4*)&As[kk][ty * 8];
            float4 a1 = *(const float4*)&As[kk][ty * 8 + 4];
            float4 b0 = *(const float4*)&Bs[kk][tx * 8];
            float4 b1 = *(const float4*)&Bs[kk][tx * 8 + 4];
            float a[8] = {a0.x, a0.y, a0.z, a0.w, a1.x, a1.y, a1.z, a1.w};
            float bb[8] = {b0.x, b0.y, b0.z, b0.w, b1.x, b1.y, b1.z, b1.w};
#pragma unroll
            for (int i = 0; i < 8; i++)
#pragma unroll
                for (int j = 0; j < 8; j++)
                    acc[i][j] = fmaf(a[i], bb[j], acc[i][j]);
        }
        __syncthreads();
    }

    // Epilogue: add bias, vectorized stores
#pragma unroll
    for (int i = 0; i < 8; i++) {
        size_t rowoff = (size_t)(m0 + ty * 8 + i) * Ndim + n0 + tx * 8;
#pragma unroll
        for (int j = 0; j < 8; j += 4) {
            float4 v;
            v.x = acc[i][j + 0] + bias[n0 + tx * 8 + j + 0];
            v.y = acc[i][j + 1] + bias[n0 + tx * 8 + j + 1];
            v.z = acc[i][j + 2] + bias[n0 + tx * 8 + j + 2];
            v.w = acc[i][j + 3] + bias[n0 + tx * 8 + j + 3];
            *(float4*)&Cc[rowoff + j] = v;
        }
    }
}

// ---------------- persistent bidirectional GRU scan ----------------
// grid = 128 CTAs: dir(2) x batch-block(8, 8 batches) x unit-block(8, 32 units)
// block = 384 threads (12 warps, 3 per SMSP).
// Weights resident in smem (96KB); h exchanged via L2 with per-(dir,bblk) group barriers.
// Dot phase: thread = (k-half, batch-group-of-4, col) with col = gate*32+uu (96 cols);
//            per k: 1 broadcast LDS128 (4 h values) + 1 LDS32 (weight) + 4 FFMA.
#define SC_SMEM_FLOATS (256*96 + 256*8 + 2*8*96)
__global__ __launch_bounds__(384, 1) void scan_k(
    const float* __restrict__ rkf, const float* __restrict__ rbf,
    const float* __restrict__ rkb, const float* __restrict__ rbb,
    unsigned* __restrict__ cnt, int layer)
{
    extern __shared__ float sm[];
    float* wk   = sm;                      // [256][96]  col = gate*32 + uu
    float* hs   = sm + 256 * 96;           // [256][8]   k-major prev-h for 8 batches
    float* part = hs + 256 * 8;            // [2][8][96] k-split partial sums

    const int cta  = blockIdx.x;
    const int dir  = cta >> 6;             // 0 fwd, 1 bwd
    const int bblk = (cta >> 3) & 7;
    const int ublk = cta & 7;
    const int b0 = bblk * 8, u0 = ublk * 32;
    const int tid = threadIdx.x;

    const float* rk = dir ? rkb : rkf;
    const float* rb = dir ? rbb : rbf;
    const float* xw = g_xw[dir];

    // Load recurrent-weight slice: wk[k][g*32+uu] = rk[k*768 + g*256 + u0+uu]
    for (int i = tid; i < 256 * 96; i += 384) {
        int k = i / 96, col = i % 96;
        int g = col >> 5, uu = col & 31;
        wk[i] = rk[(size_t)k * G_ + g * U_ + u0 + uu];
    }

    // dot-phase role
    const int kh   = tid / 192;            // k-half
    const int r2   = tid % 192;
    const int bg   = r2 / 96;              // batch group (4 batches)
    const int colT = r2 % 96;
    // gate-phase role (tid < 256): one (batch, unit) output
    const int gb  = tid >> 5;              // local batch 0..7
    const int guu = tid & 31;              // local unit 0..31
    float bz = 0.f, br = 0.f, bh = 0.f;
    if (tid < 256) {
        bz = rb[u0 + guu];
        br = rb[U_ + u0 + guu];
        bh = rb[2 * U_ + u0 + guu];
    }

    unsigned* myc = cnt + (dir * 8 + bblk);

    for (int s = 0; s < T_; s++) {
        const int t = dir ? (T_ - 1 - s) : s;

        // ---- stage prev h into hs[k][b] (k-major) ----
        if (s == 0) {
            for (int i = tid; i < 256 * 8; i += 384) hs[i] = 0.f;
        } else {
            const int tp = dir ? (t + 1) : (t - 1);
            for (int i = tid; i < 512; i += 384) {   // 512 float4
                int bb = i & 7, kf = i >> 3;         // bb varies fastest (limits STS conflicts)
                float4 v;
                if (layer == 1) {
                    v = __ldcg((const float4*)&g_h1[((size_t)(b0 + bb) * T_ + tp) * (2 * U_) + dir * U_ + kf * 4]);
                } else {
                    v = __ldcg((const float4*)&g_hs2[(s - 1) & 1][dir][b0 + bb][kf * 4]);
                }
                hs[(kf * 4 + 0) * 8 + bb] = v.x;
                hs[(kf * 4 + 1) * 8 + bb] = v.y;
                hs[(kf * 4 + 2) * 8 + bb] = v.z;
                hs[(kf * 4 + 3) * 8 + bb] = v.w;
            }
        }

        // ---- prefetch xw for gate phase (hidden under the dot) ----
        float xz = 0.f, xr = 0.f, xh = 0.f;
        if (tid < 256) {
            const float* xwp = xw + ((size_t)(b0 + gb) * T_ + t) * G_;
            xz = __ldg(xwp + u0 + guu);
            xr = __ldg(xwp + U_ + u0 + guu);
            xh = __ldg(xwp + 2 * U_ + u0 + guu);
        }
        __syncthreads();

        // ---- dot: partial inner products over this k-half ----
        {
            float a0 = 0.f, a1 = 0.f, a2 = 0.f, a3 = 0.f;
            const float* wp = wk + (kh * 128) * 96 + colT;
            const float* hp = hs + (kh * 128) * 8 + bg * 4;
#pragma unroll 8
            for (int k = 0; k < 128; k++) {
                float  w  = wp[k * 96];
                float4 h4 = *(const float4*)(hp + k * 8);
                a0 = fmaf(h4.x, w, a0);
                a1 = fmaf(h4.y, w, a1);
                a2 = fmaf(h4.z, w, a2);
                a3 = fmaf(h4.w, w, a3);
            }
            part[(kh * 8 + bg * 4 + 0) * 96 + colT] = a0;
            part[(kh * 8 + bg * 4 + 1) * 96 + colT] = a1;
            part[(kh * 8 + bg * 4 + 2) * 96 + colT] = a2;
            part[(kh * 8 + bg * 4 + 3) * 96 + colT] = a3;
        }
        __syncthreads();

        // ---- gates (threads 0..255: 8 batches x 32 units) ----
        if (tid < 256) {
            float az = bz + part[(0 * 8 + gb) * 96 + guu]      + part[(1 * 8 + gb) * 96 + guu];
            float ar = br + part[(0 * 8 + gb) * 96 + 32 + guu] + part[(1 * 8 + gb) * 96 + 32 + guu];
            float ah = bh + part[(0 * 8 + gb) * 96 + 64 + guu] + part[(1 * 8 + gb) * 96 + 64 + guu];
            float hprev = hs[(u0 + guu) * 8 + gb];
            float z  = 1.f / (1.f + expf(-(xz + az)));
            float rg = 1.f / (1.f + expf(-(xr + ar)));
            float hh = tanhf(xh + rg * ah);
            float hn = z * hprev + (1.f - z) * hh;
            if (layer == 1) {
                __stcg(&g_h1[((size_t)(b0 + gb) * T_ + t) * (2 * U_) + dir * U_ + u0 + guu], hn);
            } else {
                __stcg(&g_hs2[s & 1][dir][b0 + gb][u0 + guu], hn);
                if (s == T_ - 1) g_h2[b0 + gb][dir * U_ + u0 + guu] = hn;
            }
            __threadfence();   // release this thread's h stores
        }

        // ---- group barrier: 8 CTAs sharing (dir, bblk) ----
        if (s != T_ - 1) {
            __syncthreads();                 // all fences done
            if (tid == 0) {
                atomicAdd(myc, 1u);
                const unsigned target = 8u * (unsigned)(s + 1);
                while (*(volatile unsigned*)myc < target) { }
                __threadfence();             // acquire
            }
            __syncthreads();
        }
    }
}

// ---------------- head: softmax(h2 @ wout + bout) ----------------
__global__ void head_k(const float* __restrict__ wout, const float* __restrict__ bout,
                       float* __restrict__ out)
{
    const int b = blockIdx.x, lane = threadIdx.x;
    float acc = 0.f;
    if (lane < C_) {
        acc = bout[lane];
        for (int k = 0; k < 2 * U_; k++)
            acc = fmaf(g_h2[b][k], wout[k * C_ + lane], acc);
    }
    float v = (lane < C_) ? acc : -INFINITY;
    for (int o = 16; o; o >>= 1) v = fmaxf(v, __shfl_xor_sync(0xffffffffu, v, o));
    float e = (lane < C_) ? expf(acc - v) : 0.f;
    float ssum = e;
    for (int o = 16; o; o >>= 1) ssum += __shfl_xor_sync(0xffffffffu, ssum, o);
    if (lane < C_) out[b * C_ + lane] = e / ssum;
}

// ---------------- launch ----------------
extern "C" void kernel_launch(void* const* d_in, const int* in_sizes, int n_in,
                              void* d_out, int out_size)
{
    const int*   x    = (const int*)  d_in[0];
    const float* emb  = (const float*)d_in[1];
    const float* k1f  = (const float*)d_in[2];
    const float* rk1f = (const float*)d_in[3];
    const float* b1f  = (const float*)d_in[4];
    const float* k1b  = (const float*)d_in[5];
    const float* rk1b = (const float*)d_in[6];
    const float* b1b  = (const float*)d_in[7];
    const float* k2f  = (const float*)d_in[8];
    const float* rk2f = (const float*)d_in[9];
    const float* b2f  = (const float*)d_in[10];
    const float* k2b  = (const float*)d_in[11];
    const float* rk2b = (const float*)d_in[12];
    const float* b2b  = (const float*)d_in[13];
    const float* wout = (const float*)d_in[14];
    const float* bout = (const float*)d_in[15];
    float* out = (float*)d_out;

    float *pe, *pxw0, *pxw1, *ph1;
    unsigned *pc1, *pc2;
    cudaGetSymbolAddress((void**)&pe,   g_e);
    cudaGetSymbolAddress((void**)&pxw0, g_xw);
    pxw1 = pxw0 + (size_t)M_ * G_;
    cudaGetSymbolAddress((void**)&ph1,  g_h1);
    cudaGetSymbolAddress((void**)&pc1,  g_cnt1);
    cudaGetSymbolAddress((void**)&pc2,  g_cnt2);

    const int scan_smem = SC_SMEM_FLOATS * (int)sizeof(float);  // ~110 KB
    cudaFuncSetAttribute(scan_k, cudaFuncAttributeMaxDynamicSharedMemorySize, scan_smem);

    // 1) embedding gather (+ counter reset)
    gather_k<<<(int)(((size_t)M_ * E_ + 255) / 256), 256>>>(x, emb);

    // 2) layer-1 input projections (both directions)
    dim3 gg(G_ / 128, M_ / 128);   // (6, 256)
    sgemm_bias_k<<<gg, 256>>>(pe, k1f, b1f, pxw0, M_, G_, E_);
    sgemm_bias_k<<<gg, 256>>>(pe, k1b, b1b, pxw1, M_, G_, E_);

    // 3) layer-1 bidirectional scan -> g_h1
    scan_k<<<128, 384, scan_smem>>>(rk1f, b1f + G_, rk1b, b1b + G_, pc1, 1);

    // 4) layer-2 input projections (reuse xw buffers)
    sgemm_bias_k<<<gg, 256>>>(ph1, k2f, b2f, pxw0, M_, G_, 2 * U_);
    sgemm_bias_k<<<gg, 256>>>(ph1, k2b, b2b, pxw1, M_, G_, 2 * U_);

    // 5) layer-2 bidirectional scan -> g_h2
    scan_k<<<128, 384, scan_smem>>>(rk2f, b2f + G_, rk2b, b2b + G_, pc2, 2);

    // 6) output head
    head_k<<<B_, 32>>>(wout, bout, out);
}

// round 7
// speedup vs baseline: 1.3094x; 1.0879x over previous
#include <cuda_runtime.h>
#include <math.h>
#include <stdint.h>

// Problem constants
#define V_ 50000
#define E_ 300
#define T_ 512
#define U_ 256
#define G_ 768      // 3*U
#define B_ 64
#define C_ 20
#define M_ (B_*T_)  // 32768

// ---------------- static device scratch ----------------
__device__ float g_e [(size_t)M_ * E_];
__device__ float g_xw[2][(size_t)M_ * G_];
__device__ float g_h1[(size_t)M_ * 2 * U_];
__device__ float g_hs2[2][2][B_][U_];
__device__ float g_h2[B_][2 * U_];
__device__ unsigned g_cnt1[16];
__device__ unsigned g_cnt2[16];

__device__ __forceinline__ float tf32_rn(float x) {
    uint32_t o; asm("cvt.rna.tf32.f32 %0, %1;" : "=r"(o) : "f"(x));
    return __uint_as_float(o);
}
__device__ __forceinline__ void mma_tf32_16n8k8(float* c, const uint32_t* a, const uint32_t* b) {
    asm volatile(
        "mma.sync.aligned.m16n8k8.row.col.f32.tf32.tf32.f32 "
        "{%0,%1,%2,%3}, {%4,%5,%6,%7}, {%8,%9}, {%0,%1,%2,%3};"
        : "+f"(c[0]), "+f"(c[1]), "+f"(c[2]), "+f"(c[3])
        : "r"(a[0]), "r"(a[1]), "r"(a[2]), "r"(a[3]), "r"(b[0]), "r"(b[1]));
}

// ---------------- embedding gather (+ barrier counter reset) ----------------
__global__ void gather_k(const int* __restrict__ x, const float* __restrict__ emb) {
    if (blockIdx.x == 0 && threadIdx.x < 16) {
        g_cnt1[threadIdx.x] = 0u;
        g_cnt2[threadIdx.x] = 0u;
    }
    size_t i = (size_t)blockIdx.x * blockDim.x + threadIdx.x;
    if (i >= (size_t)M_ * E_) return;
    int bt = (int)(i / E_);
    int c  = (int)(i - (size_t)bt * E_);
    g_e[i] = emb[(size_t)x[bt] * E_ + c];
}

// ---------------- tf32 mma.sync GEMM: C[M,768] = A[M,Kreal] @ W[Kreal,768] + bias ----------------
// CTA tile 128x128, BK=32, 256 threads = 8 warps (4 M x 2 N), warp tile 32x64.
#define TS_ 136   // smem row stride (bank-conflict-free fragment loads)
__global__ void __launch_bounds__(256) mma_gemm_k(
    const float* __restrict__ A, const float* __restrict__ W,
    const float* __restrict__ bias, float* __restrict__ Cc,
    int Kreal)
{
    __shared__ float As[32 * TS_];   // [k][m]
    __shared__ float Bs[32 * TS_];   // [k][n]

    const int tid  = threadIdx.x;
    const int wid  = tid >> 5;
    const int lane = tid & 31;
    const int lq   = lane & 3;
    const int gid  = lane >> 2;
    const int m0 = blockIdx.y * 128;
    const int n0 = blockIdx.x * 128;
    const int m0w = (wid & 3) * 32;
    const int n0w = (wid >> 2) * 64;

    // bias fragment (col = n0 + n0w + nt*8 + lq*2)
    float2 bv[8];
#pragma unroll
    for (int nt = 0; nt < 8; nt++)
        bv[nt] = *(const float2*)&bias[n0 + n0w + nt * 8 + lq * 2];

    float cfr[2][8][4];
#pragma unroll
    for (int mt = 0; mt < 2; mt++)
#pragma unroll
        for (int nt = 0; nt < 8; nt++)
#pragma unroll
            for (int j = 0; j < 4; j++) cfr[mt][nt][j] = 0.f;

    const int KT = (Kreal + 31) >> 5;
    for (int kt = 0; kt < KT; kt++) {
        const int k0 = kt << 5;
        // stage A tile: 128 rows x 32 k (transpose into As[k][m])
#pragma unroll
        for (int q = 0; q < 4; q++) {
            int idx = tid + q * 256;
            int row = idx >> 3, c4 = idx & 7;
            int kk = k0 + c4 * 4;
            float4 v = make_float4(0.f, 0.f, 0.f, 0.f);
            if (kk < Kreal) v = *(const float4*)&A[(size_t)(m0 + row) * Kreal + kk];
            As[(c4 * 4 + 0) * TS_ + row] = tf32_rn(v.x);
            As[(c4 * 4 + 1) * TS_ + row] = tf32_rn(v.y);
            As[(c4 * 4 + 2) * TS_ + row] = tf32_rn(v.z);
            As[(c4 * 4 + 3) * TS_ + row] = tf32_rn(v.w);
        }
        // stage B tile: 32 k-rows x 128 n, direct from W [K][768]
#pragma unroll
        for (int q = 0; q < 4; q++) {
            int idx = tid + q * 256;
            int krow = idx >> 5, nc = idx & 31;
            float4 v = make_float4(0.f, 0.f, 0.f, 0.f);
            if (k0 + krow < Kreal)
                v = *(const float4*)&W[(size_t)(k0 + krow) * G_ + n0 + nc * 4];
            v.x = tf32_rn(v.x); v.y = tf32_rn(v.y); v.z = tf32_rn(v.z); v.w = tf32_rn(v.w);
            *(float4*)&Bs[krow * TS_ + nc * 4] = v;
        }
        __syncthreads();

#pragma unroll
        for (int ks = 0; ks < 4; ks++) {
            const int kb = ks * 8;
            const float* A0 = &As[(kb + lq) * TS_ + m0w + gid];
            const float* A1 = &As[(kb + lq + 4) * TS_ + m0w + gid];
            const float* B0 = &Bs[(kb + lq) * TS_ + n0w + gid];
            const float* B1 = &Bs[(kb + lq + 4) * TS_ + n0w + gid];
            uint32_t af[2][4], bf[8][2];
#pragma unroll
            for (int mt = 0; mt < 2; mt++) {
                af[mt][0] = __float_as_uint(A0[mt * 16]);
                af[mt][1] = __float_as_uint(A0[mt * 16 + 8]);
                af[mt][2] = __float_as_uint(A1[mt * 16]);
                af[mt][3] = __float_as_uint(A1[mt * 16 + 8]);
            }
#pragma unroll
            for (int nt = 0; nt < 8; nt++) {
                bf[nt][0] = __float_as_uint(B0[nt * 8]);
                bf[nt][1] = __float_as_uint(B1[nt * 8]);
            }
#pragma unroll
            for (int mt = 0; mt < 2; mt++)
#pragma unroll
                for (int nt = 0; nt < 8; nt++)
                    mma_tf32_16n8k8(cfr[mt][nt], af[mt], bf[nt]);
        }
        __syncthreads();
    }

    // epilogue: bias + STG.64
#pragma unroll
    for (int mt = 0; mt < 2; mt++) {
        int row = m0 + m0w + mt * 16 + gid;
#pragma unroll
        for (int nt = 0; nt < 8; nt++) {
            int col = n0 + n0w + nt * 8 + lq * 2;
            float2 v0, v1;
            v0.x = cfr[mt][nt][0] + bv[nt].x;
            v0.y = cfr[mt][nt][1] + bv[nt].y;
            v1.x = cfr[mt][nt][2] + bv[nt].x;
            v1.y = cfr[mt][nt][3] + bv[nt].y;
            *(float2*)&Cc[(size_t)row * G_ + col] = v0;
            *(float2*)&Cc[(size_t)(row + 8) * G_ + col] = v1;
        }
    }
}

// ---------------- persistent bidirectional GRU scan (unchanged from R4) ----------------
#define SC_SMEM_FLOATS (256*96 + 256*8 + 2*8*96)
__global__ __launch_bounds__(384, 1) void scan_k(
    const float* __restrict__ rkf, const float* __restrict__ rbf,
    const float* __restrict__ rkb, const float* __restrict__ rbb,
    unsigned* __restrict__ cnt, int layer)
{
    extern __shared__ float sm[];
    float* wk   = sm;                      // [256][96]
    float* hs   = sm + 256 * 96;           // [256][8]
    float* part = hs + 256 * 8;            // [2][8][96]

    const int cta  = blockIdx.x;
    const int dir  = cta >> 6;
    const int bblk = (cta >> 3) & 7;
    const int ublk = cta & 7;
    const int b0 = bblk * 8, u0 = ublk * 32;
    const int tid = threadIdx.x;

    const float* rk = dir ? rkb : rkf;
    const float* rb = dir ? rbb : rbf;
    const float* xw = g_xw[dir];

    for (int i = tid; i < 256 * 96; i += 384) {
        int k = i / 96, col = i % 96;
        int g = col >> 5, uu = col & 31;
        wk[i] = rk[(size_t)k * G_ + g * U_ + u0 + uu];
    }

    const int kh   = tid / 192;
    const int r2   = tid % 192;
    const int bg   = r2 / 96;
    const int colT = r2 % 96;
    const int gb  = tid >> 5;
    const int guu = tid & 31;
    float bz = 0.f, br = 0.f, bh = 0.f;
    if (tid < 256) {
        bz = rb[u0 + guu];
        br = rb[U_ + u0 + guu];
        bh = rb[2 * U_ + u0 + guu];
    }

    unsigned* myc = cnt + (dir * 8 + bblk);

    for (int s = 0; s < T_; s++) {
        const int t = dir ? (T_ - 1 - s) : s;

        if (s == 0) {
            for (int i = tid; i < 256 * 8; i += 384) hs[i] = 0.f;
        } else {
            const int tp = dir ? (t + 1) : (t - 1);
            for (int i = tid; i < 512; i += 384) {
                int bb = i & 7, kf = i >> 3;
                float4 v;
                if (layer == 1) {
                    v = __ldcg((const float4*)&g_h1[((size_t)(b0 + bb) * T_ + tp) * (2 * U_) + dir * U_ + kf * 4]);
                } else {
                    v = __ldcg((const float4*)&g_hs2[(s - 1) & 1][dir][b0 + bb][kf * 4]);
                }
                hs[(kf * 4 + 0) * 8 + bb] = v.x;
                hs[(kf * 4 + 1) * 8 + bb] = v.y;
                hs[(kf * 4 + 2) * 8 + bb] = v.z;
                hs[(kf * 4 + 3) * 8 + bb] = v.w;
            }
        }

        float xz = 0.f, xr = 0.f, xh = 0.f;
        if (tid < 256) {
            const float* xwp = xw + ((size_t)(b0 + gb) * T_ + t) * G_;
            xz = __ldg(xwp + u0 + guu);
            xr = __ldg(xwp + U_ + u0 + guu);
            xh = __ldg(xwp + 2 * U_ + u0 + guu);
        }
        __syncthreads();

        {
            float a0 = 0.f, a1 = 0.f, a2 = 0.f, a3 = 0.f;
            const float* wp = wk + (kh * 128) * 96 + colT;
            const float* hp = hs + (kh * 128) * 8 + bg * 4;
#pragma unroll 8
            for (int k = 0; k < 128; k++) {
                float  w  = wp[k * 96];
                float4 h4 = *(const float4*)(hp + k * 8);
                a0 = fmaf(h4.x, w, a0);
                a1 = fmaf(h4.y, w, a1);
                a2 = fmaf(h4.z, w, a2);
                a3 = fmaf(h4.w, w, a3);
            }
            part[(kh * 8 + bg * 4 + 0) * 96 + colT] = a0;
            part[(kh * 8 + bg * 4 + 1) * 96 + colT] = a1;
            part[(kh * 8 + bg * 4 + 2) * 96 + colT] = a2;
            part[(kh * 8 + bg * 4 + 3) * 96 + colT] = a3;
        }
        __syncthreads();

        if (tid < 256) {
            float az = bz + part[(0 * 8 + gb) * 96 + guu]      + part[(1 * 8 + gb) * 96 + guu];
            float ar = br + part[(0 * 8 + gb) * 96 + 32 + guu] + part[(1 * 8 + gb) * 96 + 32 + guu];
            float ah = bh + part[(0 * 8 + gb) * 96 + 64 + guu] + part[(1 * 8 + gb) * 96 + 64 + guu];
            float hprev = hs[(u0 + guu) * 8 + gb];
            float z  = 1.f / (1.f + expf(-(xz + az)));
            float rg = 1.f / (1.f + expf(-(xr + ar)));
            float hh = tanhf(xh + rg * ah);
            float hn = z * hprev + (1.f - z) * hh;
            if (layer == 1) {
                __stcg(&g_h1[((size_t)(b0 + gb) * T_ + t) * (2 * U_) + dir * U_ + u0 + guu], hn);
            } else {
                __stcg(&g_hs2[s & 1][dir][b0 + gb][u0 + guu], hn);
                if (s == T_ - 1) g_h2[b0 + gb][dir * U_ + u0 + guu] = hn;
            }
            __threadfence();
        }

        if (s != T_ - 1) {
            __syncthreads();
            if (tid == 0) {
                atomicAdd(myc, 1u);
                const unsigned target = 8u * (unsigned)(s + 1);
                while (*(volatile unsigned*)myc < target) { }
                __threadfence();
            }
            __syncthreads();
        }
    }
}

// ---------------- head: softmax(h2 @ wout + bout) ----------------
__global__ void head_k(const float* __restrict__ wout, const float* __restrict__ bout,
                       float* __restrict__ out)
{
    const int b = blockIdx.x, lane = threadIdx.x;
    float acc = 0.f;
    if (lane < C_) {
        acc = bout[lane];
        for (int k = 0; k < 2 * U_; k++)
            acc = fmaf(g_h2[b][k], wout[k * C_ + lane], acc);
    }
    float v = (lane < C_) ? acc : -INFINITY;
    for (int o = 16; o; o >>= 1) v = fmaxf(v, __shfl_xor_sync(0xffffffffu, v, o));
    float e = (lane < C_) ? expf(acc - v) : 0.f;
    float ssum = e;
    for (int o = 16; o; o >>= 1) ssum += __shfl_xor_sync(0xffffffffu, ssum, o);
    if (lane < C_) out[b * C_ + lane] = e / ssum;
}

// ---------------- launch ----------------
extern "C" void kernel_launch(void* const* d_in, const int* in_sizes, int n_in,
                              void* d_out, int out_size)
{
    const int*   x    = (const int*)  d_in[0];
    const float* emb  = (const float*)d_in[1];
    const float* k1f  = (const float*)d_in[2];
    const float* rk1f = (const float*)d_in[3];
    const float* b1f  = (const float*)d_in[4];
    const float* k1b  = (const float*)d_in[5];
    const float* rk1b = (const float*)d_in[6];
    const float* b1b  = (const float*)d_in[7];
    const float* k2f  = (const float*)d_in[8];
    const float* rk2f = (const float*)d_in[9];
    const float* b2f  = (const float*)d_in[10];
    const float* k2b  = (const float*)d_in[11];
    const float* rk2b = (const float*)d_in[12];
    const float* b2b  = (const float*)d_in[13];
    const float* wout = (const float*)d_in[14];
    const float* bout = (const float*)d_in[15];
    float* out = (float*)d_out;

    float *pe, *pxw0, *pxw1, *ph1;
    unsigned *pc1, *pc2;
    cudaGetSymbolAddress((void**)&pe,   g_e);
    cudaGetSymbolAddress((void**)&pxw0, g_xw);
    pxw1 = pxw0 + (size_t)M_ * G_;
    cudaGetSymbolAddress((void**)&ph1,  g_h1);
    cudaGetSymbolAddress((void**)&pc1,  g_cnt1);
    cudaGetSymbolAddress((void**)&pc2,  g_cnt2);

    const int scan_smem = SC_SMEM_FLOATS * (int)sizeof(float);
    cudaFuncSetAttribute(scan_k, cudaFuncAttributeMaxDynamicSharedMemorySize, scan_smem);

    dim3 gg(G_ / 128, M_ / 128);   // (6, 256)

    // 1) embedding gather (+ counter reset)
    gather_k<<<(int)(((size_t)M_ * E_ + 255) / 256), 256>>>(x, emb);

    // 2) layer-1 input projections (tf32 mma)
    mma_gemm_k<<<gg, 256>>>(pe, k1f, b1f, pxw0, E_);
    mma_gemm_k<<<gg, 256>>>(pe, k1b, b1b, pxw1, E_);

    // 3) layer-1 bidirectional scan -> g_h1
    scan_k<<<128, 384, scan_smem>>>(rk1f, b1f + G_, rk1b, b1b + G_, pc1, 1);

    // 4) layer-2 input projections
    mma_gemm_k<<<gg, 256>>>(ph1, k2f, b2f, pxw0, 2 * U_);
    mma_gemm_k<<<gg, 256>>>(ph1, k2b, b2b, pxw1, 2 * U_);

    // 5) layer-2 bidirectional scan -> g_h2
    scan_k<<<128, 384, scan_smem>>>(rk2f, b2f + G_, rk2b, b2b + G_, pc2, 2);

    // 6) output head
    head_k<<<B_, 32>>>(wout, bout, out);
}

// round 8
// speedup vs baseline: 1.3931x; 1.0640x over previous
#include <cuda_runtime.h>
#include <math.h>
#include <stdint.h>

// Problem constants
#define V_ 50000
#define E_ 300
#define T_ 512
#define U_ 256
#define G_ 768      // 3*U
#define B_ 64
#define C_ 20
#define M_ (B_*T_)  // 32768

// ---------------- static device scratch ----------------
__device__ float g_e [(size_t)M_ * E_];
__device__ float g_xw[2][(size_t)M_ * G_];
__device__ float g_h1[(size_t)M_ * 2 * U_];
__device__ float g_hs2[2][2][B_][U_];
__device__ float g_h2[B_][2 * U_];
__device__ unsigned g_cnt1[16];
__device__ unsigned g_cnt2[16];

__device__ __forceinline__ uint32_t smem_u32(const void* p) {
    uint32_t a;
    asm("{ .reg .u64 t; cvta.to.shared.u64 t, %1; cvt.u32.u64 %0, t; }" : "=r"(a) : "l"(p));
    return a;
}
__device__ __forceinline__ void mma_tf32_16n8k8(float* c, const uint32_t* a, const uint32_t* b) {
    asm volatile(
        "mma.sync.aligned.m16n8k8.row.col.f32.tf32.tf32.f32 "
        "{%0,%1,%2,%3}, {%4,%5,%6,%7}, {%8,%9}, {%0,%1,%2,%3};"
        : "+f"(c[0]), "+f"(c[1]), "+f"(c[2]), "+f"(c[3])
        : "r"(a[0]), "r"(a[1]), "r"(a[2]), "r"(a[3]), "r"(b[0]), "r"(b[1]));
}
#define CP_COMMIT() asm volatile("cp.async.commit_group;" ::: "memory")
#define CP_WAIT(n)  asm volatile("cp.async.wait_group %0;" :: "n"(n) : "memory")

// ---------------- embedding gather (+ barrier counter reset) ----------------
__global__ void gather_k(const int* __restrict__ x, const float* __restrict__ emb) {
    if (blockIdx.x == 0 && threadIdx.x < 16) {
        g_cnt1[threadIdx.x] = 0u;
        g_cnt2[threadIdx.x] = 0u;
    }
    size_t i = (size_t)blockIdx.x * blockDim.x + threadIdx.x;
    if (i >= (size_t)M_ * E_) return;
    int bt = (int)(i / E_);
    int c  = (int)(i - (size_t)bt * E_);
    g_e[i] = emb[(size_t)x[bt] * E_ + c];
}

// ---------------- tf32 mma.sync GEMM, cp.async double-buffered ----------------
// C[M,768] = A[M,Kreal] @ W[Kreal,768] + bias
// CTA tile 128x128, BK=32, 256 threads = 8 warps (4 M x 2 N), warp tile 32x64.
// As [128][36] (m-major, stride 36 => conflict-free frag loads), Bs [32][136].
#define SA_ 36
#define SB_ 136
#define A_FLOATS (128 * SA_)          // 4608
#define B_FLOATS (32 * SB_)           // 4352
#define BUF_FLOATS (A_FLOATS + B_FLOATS)
#define GEMM_SMEM (2 * BUF_FLOATS * 4)  // 71680 bytes

__device__ __forceinline__ void stage_tile(
    uint32_t sa, uint32_t sb, const float* __restrict__ A, const float* __restrict__ W,
    int m0, int n0, int k0, int Kreal, int tid)
{
    // A: 128 rows x 32 cols, 64B contiguous per thread
    {
        int arow  = tid >> 1;
        int aseg0 = (tid & 1) * 4;
        const float* arow_p = A + (size_t)(m0 + arow) * Kreal;
#pragma unroll
        for (int q = 0; q < 4; q++) {
            int col = k0 + (aseg0 + q) * 4;
            int szf = Kreal - col; szf = szf < 0 ? 0 : (szf > 4 ? 4 : szf);
            int sz = szf * 4;
            const float* src = arow_p + (sz ? col : 0);
            uint32_t dst = sa + (uint32_t)(arow * SA_ + (aseg0 + q) * 4) * 4u;
            asm volatile("cp.async.cg.shared.global [%0], [%1], 16, %2;"
                         :: "r"(dst), "l"(src), "r"(sz) : "memory");
        }
    }
    // B: 32 k-rows x 128 cols, 64B contiguous per thread
    {
        int krow  = tid >> 3;
        int bseg0 = (tid & 7) * 4;
        int kr = k0 + krow;
        int sz = (kr < Kreal) ? 16 : 0;
        const float* brow_p = W + (size_t)(sz ? kr : 0) * G_ + n0;
#pragma unroll
        for (int q = 0; q < 4; q++) {
            uint32_t dst = sb + (uint32_t)(krow * SB_ + (bseg0 + q) * 4) * 4u;
            asm volatile("cp.async.cg.shared.global [%0], [%1], 16, %2;"
                         :: "r"(dst), "l"(brow_p + (bseg0 + q) * 4), "r"(sz) : "memory");
        }
    }
}

__global__ void __launch_bounds__(256, 2) mma_gemm_k(
    const float* __restrict__ A, const float* __restrict__ W,
    const float* __restrict__ bias, float* __restrict__ Cc,
    int Kreal)
{
    extern __shared__ float smf[];
    const uint32_t sbase = smem_u32(smf);

    const int tid  = threadIdx.x;
    const int wid  = tid >> 5;
    const int lane = tid & 31;
    const int lq   = lane & 3;
    const int gid  = lane >> 2;
    const int m0 = blockIdx.y * 128;
    const int n0 = blockIdx.x * 128;
    const int m0w = (wid & 3) * 32;
    const int n0w = (wid >> 2) * 64;

    float2 bv[8];
#pragma unroll
    for (int nt = 0; nt < 8; nt++)
        bv[nt] = *(const float2*)&bias[n0 + n0w + nt * 8 + lq * 2];

    float cfr[2][8][4];
#pragma unroll
    for (int mt = 0; mt < 2; mt++)
#pragma unroll
        for (int nt = 0; nt < 8; nt++)
#pragma unroll
            for (int j = 0; j < 4; j++) cfr[mt][nt][j] = 0.f;

    const int KT = (Kreal + 31) >> 5;

    // prologue: stage tile 0 into buffer 0
    stage_tile(sbase, sbase + A_FLOATS * 4u, A, W, m0, n0, 0, Kreal, tid);
    CP_COMMIT();

    for (int kt = 0; kt < KT; kt++) {
        const int cur = kt & 1;
        if (kt + 1 < KT) {
            uint32_t nb = sbase + (uint32_t)(((kt + 1) & 1) * BUF_FLOATS) * 4u;
            stage_tile(nb, nb + A_FLOATS * 4u, A, W, m0, n0, (kt + 1) << 5, Kreal, tid);
            CP_COMMIT();
            CP_WAIT(1);
        } else {
            CP_WAIT(0);
        }
        __syncthreads();

        const float* As_ = smf + cur * BUF_FLOATS;
        const float* Bs_ = As_ + A_FLOATS;

#pragma unroll
        for (int ks = 0; ks < 4; ks++) {
            const int kb = ks * 8;
            uint32_t af[2][4], bf[8][2];
#pragma unroll
            for (int mt = 0; mt < 2; mt++) {
                const float* ap = As_ + (m0w + mt * 16 + gid) * SA_ + kb + lq;
                af[mt][0] = __float_as_uint(ap[0]);
                af[mt][1] = __float_as_uint(ap[8 * SA_]);
                af[mt][2] = __float_as_uint(ap[4]);
                af[mt][3] = __float_as_uint(ap[8 * SA_ + 4]);
            }
#pragma unroll
            for (int nt = 0; nt < 8; nt++) {
                const float* bp = Bs_ + (kb + lq) * SB_ + n0w + nt * 8 + gid;
                bf[nt][0] = __float_as_uint(bp[0]);
                bf[nt][1] = __float_as_uint(bp[4 * SB_]);
            }
#pragma unroll
            for (int mt = 0; mt < 2; mt++)
#pragma unroll
                for (int nt = 0; nt < 8; nt++)
                    mma_tf32_16n8k8(cfr[mt][nt], af[mt], bf[nt]);
        }
        __syncthreads();
    }

    // epilogue: bias + STG.64
#pragma unroll
    for (int mt = 0; mt < 2; mt++) {
        int row = m0 + m0w + mt * 16 + gid;
#pragma unroll
        for (int nt = 0; nt < 8; nt++) {
            int col = n0 + n0w + nt * 8 + lq * 2;
            float2 v0, v1;
            v0.x = cfr[mt][nt][0] + bv[nt].x;
            v0.y = cfr[mt][nt][1] + bv[nt].y;
            v1.x = cfr[mt][nt][2] + bv[nt].x;
            v1.y = cfr[mt][nt][3] + bv[nt].y;
            *(float2*)&Cc[(size_t)row * G_ + col] = v0;
            *(float2*)&Cc[(size_t)(row + 8) * G_ + col] = v1;
        }
    }
}

// ---------------- persistent bidirectional GRU scan ----------------
#define SC_SMEM_FLOATS (256*96 + 256*8 + 2*8*96)
__global__ __launch_bounds__(384, 1) void scan_k(
    const float* __restrict__ rkf, const float* __restrict__ rbf,
    const float* __restrict__ rkb, const float* __restrict__ rbb,
    unsigned* __restrict__ cnt, int layer)
{
    extern __shared__ float sm[];
    float* wk   = sm;                      // [256][96]
    float* hs   = sm + 256 * 96;           // [256][8]
    float* part = hs + 256 * 8;            // [2][8][96]

    const int cta  = blockIdx.x;
    const int dir  = cta >> 6;
    const int bblk = (cta >> 3) & 7;
    const int ublk = cta & 7;
    const int b0 = bblk * 8, u0 = ublk * 32;
    const int tid = threadIdx.x;

    const float* rk = dir ? rkb : rkf;
    const float* rb = dir ? rbb : rbf;
    const float* xw = g_xw[dir];

    for (int i = tid; i < 256 * 96; i += 384) {
        int k = i / 96, col = i % 96;
        int g = col >> 5, uu = col & 31;
        wk[i] = rk[(size_t)k * G_ + g * U_ + u0 + uu];
    }

    const int kh   = tid / 192;
    const int r2   = tid % 192;
    const int bg   = r2 / 96;
    const int colT = r2 % 96;
    const int gb  = tid >> 5;
    const int guu = tid & 31;
    float bz = 0.f, br = 0.f, bh = 0.f;
    if (tid < 256) {
        bz = rb[u0 + guu];
        br = rb[U_ + u0 + guu];
        bh = rb[2 * U_ + u0 + guu];
    }

    unsigned* myc = cnt + (dir * 8 + bblk);

    for (int s = 0; s < T_; s++) {
        const int t = dir ? (T_ - 1 - s) : s;

        if (s == 0) {
            for (int i = tid; i < 256 * 8; i += 384) hs[i] = 0.f;
        } else {
            const int tp = dir ? (t + 1) : (t - 1);
            for (int i = tid; i < 512; i += 384) {
                int bb = i & 7, kf = i >> 3;
                float4 v;
                if (layer == 1) {
                    v = __ldcg((const float4*)&g_h1[((size_t)(b0 + bb) * T_ + tp) * (2 * U_) + dir * U_ + kf * 4]);
                } else {
                    v = __ldcg((const float4*)&g_hs2[(s - 1) & 1][dir][b0 + bb][kf * 4]);
                }
                hs[(kf * 4 + 0) * 8 + bb] = v.x;
                hs[(kf * 4 + 1) * 8 + bb] = v.y;
                hs[(kf * 4 + 2) * 8 + bb] = v.z;
                hs[(kf * 4 + 3) * 8 + bb] = v.w;
            }
        }

        float xz = 0.f, xr = 0.f, xh = 0.f;
        if (tid < 256) {
            const float* xwp = xw + ((size_t)(b0 + gb) * T_ + t) * G_;
            xz = __ldg(xwp + u0 + guu);
            xr = __ldg(xwp + U_ + u0 + guu);
            xh = __ldg(xwp + 2 * U_ + u0 + guu);
        }
        __syncthreads();

        {
            float a0 = 0.f, a1 = 0.f, a2 = 0.f, a3 = 0.f;
            const float* wp = wk + (kh * 128) * 96 + colT;
            const float* hp = hs + (kh * 128) * 8 + bg * 4;
#pragma unroll 8
            for (int k = 0; k < 128; k++) {
                float  w  = wp[k * 96];
                float4 h4 = *(const float4*)(hp + k * 8);
                a0 = fmaf(h4.x, w, a0);
                a1 = fmaf(h4.y, w, a1);
                a2 = fmaf(h4.z, w, a2);
                a3 = fmaf(h4.w, w, a3);
            }
            part[(kh * 8 + bg * 4 + 0) * 96 + colT] = a0;
            part[(kh * 8 + bg * 4 + 1) * 96 + colT] = a1;
            part[(kh * 8 + bg * 4 + 2) * 96 + colT] = a2;
            part[(kh * 8 + bg * 4 + 3) * 96 + colT] = a3;
        }
        __syncthreads();

        if (tid < 256) {
            float az = bz + part[(0 * 8 + gb) * 96 + guu]      + part[(1 * 8 + gb) * 96 + guu];
            float ar = br + part[(0 * 8 + gb) * 96 + 32 + guu] + part[(1 * 8 + gb) * 96 + 32 + guu];
            float ah = bh + part[(0 * 8 + gb) * 96 + 64 + guu] + part[(1 * 8 + gb) * 96 + 64 + guu];
            float hprev = hs[(u0 + guu) * 8 + gb];
            float z  = 1.f / (1.f + expf(-(xz + az)));
            float rg = 1.f / (1.f + expf(-(xr + ar)));
            float hh = tanhf(xh + rg * ah);
            float hn = z * hprev + (1.f - z) * hh;
            if (layer == 1) {
                __stcg(&g_h1[((size_t)(b0 + gb) * T_ + t) * (2 * U_) + dir * U_ + u0 + guu], hn);
            } else {
                __stcg(&g_hs2[s & 1][dir][b0 + gb][u0 + guu], hn);
                if (s == T_ - 1) g_h2[b0 + gb][dir * U_ + u0 + guu] = hn;
            }
        }

        // group barrier: single cumulative release fence by tid0 (PTX fences are
        // cumulative; __syncthreads orders all threads' stcg before tid0's fence)
        if (s != T_ - 1) {
            __syncthreads();
            if (tid == 0) {
                __threadfence();                       // release (cumulative)
                atomicAdd(myc, 1u);
                const unsigned target = 8u * (unsigned)(s + 1);
                while (*(volatile unsigned*)myc < target) { }
                __threadfence();                       // acquire
            }
            __syncthreads();
        }
    }
}

// ---------------- head: softmax(h2 @ wout + bout) ----------------
__global__ void head_k(const float* __restrict__ wout, const float* __restrict__ bout,
                       float* __restrict__ out)
{
    const int b = blockIdx.x, lane = threadIdx.x;
    float acc = 0.f;
    if (lane < C_) {
        acc = bout[lane];
        for (int k = 0; k < 2 * U_; k++)
            acc = fmaf(g_h2[b][k], wout[k * C_ + lane], acc);
    }
    float v = (lane < C_) ? acc : -INFINITY;
    for (int o = 16; o; o >>= 1) v = fmaxf(v, __shfl_xor_sync(0xffffffffu, v, o));
    float e = (lane < C_) ? expf(acc - v) : 0.f;
    float ssum = e;
    for (int o = 16; o; o >>= 1) ssum += __shfl_xor_sync(0xffffffffu, ssum, o);
    if (lane < C_) out[b * C_ + lane] = e / ssum;
}

// ---------------- launch ----------------
extern "C" void kernel_launch(void* const* d_in, const int* in_sizes, int n_in,
                              void* d_out, int out_size)
{
    const int*   x    = (const int*)  d_in[0];
    const float* emb  = (const float*)d_in[1];
    const float* k1f  = (const float*)d_in[2];
    const float* rk1f = (const float*)d_in[3];
    const float* b1f  = (const float*)d_in[4];
    const float* k1b  = (const float*)d_in[5];
    const float* rk1b = (const float*)d_in[6];
    const float* b1b  = (const float*)d_in[7];
    const float* k2f  = (const float*)d_in[8];
    const float* rk2f = (const float*)d_in[9];
    const float* b2f  = (const float*)d_in[10];
    const float* k2b  = (const float*)d_in[11];
    const float* rk2b = (const float*)d_in[12];
    const float* b2b  = (const float*)d_in[13];
    const float* wout = (const float*)d_in[14];
    const float* bout = (const float*)d_in[15];
    float* out = (float*)d_out;

    float *pe, *pxw0, *pxw1, *ph1;
    unsigned *pc1, *pc2;
    cudaGetSymbolAddress((void**)&pe,   g_e);
    cudaGetSymbolAddress((void**)&pxw0, g_xw);
    pxw1 = pxw0 + (size_t)M_ * G_;
    cudaGetSymbolAddress((void**)&ph1,  g_h1);
    cudaGetSymbolAddress((void**)&pc1,  g_cnt1);
    cudaGetSymbolAddress((void**)&pc2,  g_cnt2);

    const int scan_smem = SC_SMEM_FLOATS * (int)sizeof(float);
    cudaFuncSetAttribute(scan_k,     cudaFuncAttributeMaxDynamicSharedMemorySize, scan_smem);
    cudaFuncSetAttribute(mma_gemm_k, cudaFuncAttributeMaxDynamicSharedMemorySize, GEMM_SMEM);

    dim3 gg(G_ / 128, M_ / 128);   // (6, 256)

    // 1) embedding gather (+ counter reset)
    gather_k<<<(int)(((size_t)M_ * E_ + 255) / 256), 256>>>(x, emb);

    // 2) layer-1 input projections (tf32 mma, cp.async pipelined)
    mma_gemm_k<<<gg, 256, GEMM_SMEM>>>(pe, k1f, b1f, pxw0, E_);
    mma_gemm_k<<<gg, 256, GEMM_SMEM>>>(pe, k1b, b1b, pxw1, E_);

    // 3) layer-1 bidirectional scan -> g_h1
    scan_k<<<128, 384, scan_smem>>>(rk1f, b1f + G_, rk1b, b1b + G_, pc1, 1);

    // 4) layer-2 input projections
    mma_gemm_k<<<gg, 256, GEMM_SMEM>>>(ph1, k2f, b2f, pxw0, 2 * U_);
    mma_gemm_k<<<gg, 256, GEMM_SMEM>>>(ph1, k2b, b2b, pxw1, 2 * U_);

    // 5) layer-2 bidirectional scan -> g_h2
    scan_k<<<128, 384, scan_smem>>>(rk2f, b2f + G_, rk2b, b2b + G_, pc2, 2);

    // 6) output head
    head_k<<<B_, 32>>>(wout, bout, out);
}